// round 10
// baseline (speedup 1.0000x reference)
#include <cuda_runtime.h>
#include <cuda_bf16.h>
#include <cstdint>

// ---------------------------------------------------------------------------
// Problem constants
// ---------------------------------------------------------------------------
#define BATCH   32768
#define IN_DIM  1024
#define XROW    3072      // x row stride (3*32*32)
#define EMBED   16
#define TINY    16
#define NEXP    4
#define OUTD    1000
#define KC      72        // padded K for the big GEMM (64 hg + 4 gate + 4 zero)
#define NPAD    1008      // 1000 padded to multiple of 144

// Scratch (device globals — no allocations allowed)
__device__ __align__(16) float g_A[BATCH * KC];        // 9.4 MB  A matrix (tf32-rounded fp32)
__device__ __align__(16) float g_Wc[KC * NPAD];        // 290 KB  combined W2|b2 matrix

// ---------------------------------------------------------------------------
// Helpers
// ---------------------------------------------------------------------------
__device__ __forceinline__ float tf32r(float v) {
    unsigned u;
    asm("cvt.rna.tf32.f32 %0, %1;" : "=r"(u) : "f"(v));
    return __uint_as_float(u);
}

__device__ __forceinline__ void ffma2(unsigned long long& acc,
                                      unsigned long long a,
                                      unsigned long long b) {
    asm("fma.rn.f32x2 %0, %1, %2, %0;" : "+l"(acc) : "l"(a), "l"(b));
}

__device__ __forceinline__ void mma_tf32(float* c, const unsigned* a,
                                         unsigned b0, unsigned b1) {
    asm volatile(
        "mma.sync.aligned.m16n8k8.row.col.f32.tf32.tf32.f32 "
        "{%0,%1,%2,%3}, {%4,%5,%6,%7}, {%8,%9}, {%0,%1,%2,%3};"
        : "+f"(c[0]), "+f"(c[1]), "+f"(c[2]), "+f"(c[3])
        : "r"(a[0]), "r"(a[1]), "r"(a[2]), "r"(a[3]), "r"(b0), "r"(b1));
}

// ---------------------------------------------------------------------------
// Kernel 0: build Wc[72][1008] = [W2 (64 rows) | b2 (4 rows) | zeros], tf32-rounded
// W2 is [4][16][1000] row-major => flattened it is exactly [64][1000].
// ---------------------------------------------------------------------------
__global__ void k_prep(const float* __restrict__ W2, const float* __restrict__ b2) {
    int idx = blockIdx.x * 256 + threadIdx.x;
    if (idx >= KC * NPAD) return;
    int k = idx / NPAD, n = idx % NPAD;
    float v = 0.f;
    if (n < OUTD) {
        if (k < 64)      v = W2[k * OUTD + n];
        else if (k < 68) v = b2[(k - 64) * OUTD + n];
    }
    g_Wc[idx] = tf32r(v);
}

// ---------------------------------------------------------------------------
// Kernel 1: fused embed + gate + experts-hidden.  One thread per batch row.
// Stage 1 in exact fp32 with packed f32x2 FMAs; W_embed cached in smem;
// x staged through smem in 32-col chunks with register prefetch (double buffer).
// Epilogue computes gate softmax + h, writes A row (72 floats, tf32-rounded).
// ---------------------------------------------------------------------------
#define K1_SMEM_FLOATS (16384 /*Wemb*/ + 256*36 /*x chunk*/ + 1024 + 64 + 64 + 16 + 4)

__global__ void __launch_bounds__(256)
k_embed(const float* __restrict__ x,
        const float* __restrict__ We, const float* __restrict__ be,
        const float* __restrict__ W1, const float* __restrict__ b1,
        const float* __restrict__ Wg, const float* __restrict__ bg) {
    extern __shared__ float sm[];
    float* wsf  = sm;                 // W_embed as [16][1024] (== [16][256] float4)
    float* xs   = sm + 16384;         // [256][36]  (pad 36 => conflict-free)
    float* sW1  = xs + 256 * 36;      // [4][16][16]
    float* sWg  = sW1 + 1024;         // [4][16]
    float* sb1  = sWg + 64;           // [4][16]
    float* sbe  = sb1 + 64;           // [16]
    float* sbg  = sbe + 16;           // [4]

    const int tid = threadIdx.x;

    // small copies
    for (int i = tid; i < 1024; i += 256) sW1[i] = W1[i];
    if (tid < 64) sWg[tid] = Wg[tid];
    if (tid < 64) sb1[tid] = b1[tid];
    if (tid < 16) sbe[tid] = be[tid];
    if (tid < 4)  sbg[tid] = bg[tid];
    // W_embed: 16*1024 floats = 4096 float4, same linear layout as global
    {
        const float4* src = (const float4*)We;
        float4* dst = (float4*)wsf;
        for (int i = tid; i < 4096; i += 256) dst[i] = src[i];
    }

    const float* xbase = x + (size_t)blockIdx.x * 256 * XROW;

    // prefetch chunk 0 into registers (coalesced: 8 lanes cover one 128B row seg)
    float4 pre[8];
#pragma unroll
    for (int i = 0; i < 8; i++) {
        int idx = i * 256 + tid;
        int r = idx >> 3, c4 = idx & 7;
        pre[i] = *(const float4*)(xbase + (size_t)r * XROW + c4 * 4);
    }

    unsigned long long acc[EMBED];
#pragma unroll
    for (int j = 0; j < EMBED; j++) acc[j] = 0ull;

    __syncthreads();   // smem weight copies ready

    for (int kc = 0; kc < 32; kc++) {
        // store prefetched chunk
#pragma unroll
        for (int i = 0; i < 8; i++) {
            int idx = i * 256 + tid;
            int r = idx >> 3, c4 = idx & 7;
            *(float4*)(xs + r * 36 + c4 * 4) = pre[i];
        }
        __syncthreads();
        // prefetch next chunk
        if (kc + 1 < 32) {
#pragma unroll
            for (int i = 0; i < 8; i++) {
                int idx = i * 256 + tid;
                int r = idx >> 3, c4 = idx & 7;
                pre[i] = *(const float4*)(xbase + (size_t)r * XROW + (kc + 1) * 32 + c4 * 4);
            }
        }
        // compute: this thread's row = tid (local)
        const ulonglong2* myx = (const ulonglong2*)(xs + tid * 36);
        const ulonglong2* w2p = (const ulonglong2*)wsf;
#pragma unroll
        for (int c4 = 0; c4 < 8; c4++) {
            ulonglong2 xv = myx[c4];
#pragma unroll
            for (int j = 0; j < EMBED; j++) {
                ulonglong2 wv = w2p[j * 256 + kc * 8 + c4];   // broadcast LDS.128
                ffma2(acc[j], xv.x, wv.x);
                ffma2(acc[j], xv.y, wv.y);
            }
        }
        __syncthreads();
    }

    // ---- epilogue (per row) ----
    float e[EMBED];
#pragma unroll
    for (int j = 0; j < EMBED; j++) {
        float lo, hi;
        asm("mov.b64 {%0,%1}, %2;" : "=f"(lo), "=f"(hi) : "l"(acc[j]));
        float v = lo + hi + sbe[j];
        e[j] = v > 0.f ? v : 0.f;
    }
    // gate
    float g[NEXP];
#pragma unroll
    for (int ex = 0; ex < NEXP; ex++) {
        float s = sbg[ex];
#pragma unroll
        for (int j = 0; j < EMBED; j++) s += e[j] * sWg[ex * EMBED + j];
        g[ex] = s;
    }
    float mx = fmaxf(fmaxf(g[0], g[1]), fmaxf(g[2], g[3]));
    float den = 0.f;
#pragma unroll
    for (int ex = 0; ex < NEXP; ex++) { g[ex] = __expf(g[ex] - mx); den += g[ex]; }
    float inv = 1.0f / den;
#pragma unroll
    for (int ex = 0; ex < NEXP; ex++) g[ex] *= inv;

    // experts hidden, gated, write A row
    int row = blockIdx.x * 256 + tid;
    float* Arow = g_A + (size_t)row * KC;
#pragma unroll
    for (int ex = 0; ex < NEXP; ex++) {
#pragma unroll
        for (int t = 0; t < TINY; t++) {
            float s = sb1[ex * TINY + t];
#pragma unroll
            for (int j = 0; j < EMBED; j++)
                s += e[j] * sW1[(ex * EMBED + j) * TINY + t];
            s = s > 0.f ? s : 0.f;
            Arow[ex * TINY + t] = tf32r(s * g[ex]);
        }
        Arow[64 + ex] = tf32r(g[ex]);
    }
    Arow[68] = 0.f; Arow[69] = 0.f; Arow[70] = 0.f; Arow[71] = 0.f;
}

// ---------------------------------------------------------------------------
// Kernel 2: out[32768,1000] = A[32768,72] @ Wc[72,1008]  (tf32 mma, fp32 accum)
// CTA: 256 threads = 8 warps (4 M-groups x 2 N-groups). Tile M=128, N=144.
// Both tiles staged in smem with conflict-free padded strides (A:76, W:152).
// ---------------------------------------------------------------------------
#define K2_SMEM_FLOATS (72 * 152 + 128 * 76)

__global__ void __launch_bounds__(256)
k_gemm(float* __restrict__ out) {
    extern __shared__ float sm[];
    float* Ws = sm;               // [72][152]
    float* As = sm + 72 * 152;    // [128][76]

    const int tid = threadIdx.x;
    const int mb = blockIdx.x, nb = blockIdx.y;

    // W tile: 72 rows x 144 cols
    for (int i = tid; i < 72 * 36; i += 256) {
        int r = i / 36, c4 = i % 36;
        float4 v = *(const float4*)(g_Wc + r * NPAD + nb * 144 + c4 * 4);
        *(float4*)(Ws + r * 152 + c4 * 4) = v;
    }
    // A tile: 128 rows x 72 cols
    for (int i = tid; i < 128 * 18; i += 256) {
        int r = i / 18, c4 = i % 18;
        float4 v = *(const float4*)(g_A + ((size_t)(mb * 128 + r)) * KC + c4 * 4);
        *(float4*)(As + r * 76 + c4 * 4) = v;
    }
    __syncthreads();

    const int wid = tid >> 5, lane = tid & 31;
    const int wm = wid & 3, wn = wid >> 2;
    const int mbase = wm * 32, nbase = wn * 72;
    const int tig = lane & 3, grp = lane >> 2;

    float c[2][9][4];
#pragma unroll
    for (int m = 0; m < 2; m++)
#pragma unroll
        for (int n = 0; n < 9; n++)
#pragma unroll
            for (int q = 0; q < 4; q++) c[m][n][q] = 0.f;

#pragma unroll
    for (int k8 = 0; k8 < 9; k8++) {
        const int k0 = k8 * 8 + tig;
        unsigned a[2][4];
#pragma unroll
        for (int m = 0; m < 2; m++) {
            int r = mbase + m * 16 + grp;
            a[m][0] = __float_as_uint(As[r * 76 + k0]);
            a[m][1] = __float_as_uint(As[(r + 8) * 76 + k0]);
            a[m][2] = __float_as_uint(As[r * 76 + k0 + 4]);
            a[m][3] = __float_as_uint(As[(r + 8) * 76 + k0 + 4]);
        }
#pragma unroll
        for (int n8 = 0; n8 < 9; n8++) {
            int nc = nbase + n8 * 8 + grp;
            unsigned b0 = __float_as_uint(Ws[k0 * 152 + nc]);
            unsigned b1 = __float_as_uint(Ws[(k0 + 4) * 152 + nc]);
            mma_tf32(c[0][n8], a[0], b0, b1);
            mma_tf32(c[1][n8], a[1], b0, b1);
        }
    }

    // epilogue: predicated float2 stores (gc even; 1000 even => pairs all-or-none)
#pragma unroll
    for (int m = 0; m < 2; m++) {
        int gr = mb * 128 + mbase + m * 16 + grp;
#pragma unroll
        for (int n8 = 0; n8 < 9; n8++) {
            int gc = nb * 144 + nbase + n8 * 8 + 2 * tig;
            if (gc < OUTD) {
                *(float2*)(out + (size_t)gr * OUTD + gc) =
                    make_float2(c[m][n8][0], c[m][n8][1]);
                *(float2*)(out + (size_t)(gr + 8) * OUTD + gc) =
                    make_float2(c[m][n8][2], c[m][n8][3]);
            }
        }
    }
}

// ---------------------------------------------------------------------------
// Launch
// ---------------------------------------------------------------------------
extern "C" void kernel_launch(void* const* d_in, const int* in_sizes, int n_in,
                              void* d_out, int out_size) {
    const float* x   = (const float*)d_in[0];
    const float* We  = (const float*)d_in[1];
    const float* be  = (const float*)d_in[2];
    const float* W1  = (const float*)d_in[3];
    const float* b1  = (const float*)d_in[4];
    const float* W2  = (const float*)d_in[5];
    const float* b2  = (const float*)d_in[6];
    const float* Wg  = (const float*)d_in[7];
    const float* bg  = (const float*)d_in[8];
    float* out = (float*)d_out;

    static bool attr_done = false;  // attribute setting only; deterministic & idempotent
    if (!attr_done) {
        cudaFuncSetAttribute(k_embed, cudaFuncAttributeMaxDynamicSharedMemorySize,
                             K1_SMEM_FLOATS * 4);
        cudaFuncSetAttribute(k_gemm, cudaFuncAttributeMaxDynamicSharedMemorySize,
                             K2_SMEM_FLOATS * 4);
        attr_done = true;
    }

    k_prep<<<(KC * NPAD + 255) / 256, 256>>>(W2, b2);
    k_embed<<<BATCH / 256, 256, K1_SMEM_FLOATS * 4>>>(x, We, be, W1, b1, Wg, bg);
    k_gemm<<<dim3(BATCH / 128, NPAD / 144), 256, K2_SMEM_FLOATS * 4>>>(out);
}